// round 9
// baseline (speedup 1.0000x reference)
#include <cuda_runtime.h>
#include <cstdint>

// GeometricLoss via spatial grid, R9:
//  K1 build (1 CTA): bbox -> smem bin count -> shfl-based prefix scan (2
//     barriers) -> scatter into g_pts4 {x,y,pid,0} + g_cellinfo {start,count}.
//  K2 search: one warp per query; disk/ring rows become CONTIGUOUS slot
//     ranges (row-major counting sort), scanned with lanes parallel over
//     points (coalesced, uniform). Exact warp merge + exact ring bound.
// Selection over unique keys (d2_bits<<32)|pid -> order-independent, exact
// jax.lax.top_k semantics (low-index tie-break), deterministic output.

#define NPTS 8192
#define NCH 16
#define KNN 5
#define G 64
#define NCELL (G * G)
#define FULLM 0xFFFFFFFFu
typedef unsigned long long ull;
#define SENT 0xFFFFFFFFFFFFFFFFULL

__device__ float4 g_pts4[NPTS];       // {x, y, bitcast(pid), 0}
__device__ int2   g_cellinfo[NCELL];  // {start, count}
__device__ float  g_partial[NPTS];
__device__ unsigned g_ticket;
__device__ float g_minx, g_miny, g_invw, g_invh, g_cwmin;

// ======================= K1: build (single CTA) =======================
__global__ __launch_bounds__(1024, 1)
void build_kernel(const float2* __restrict__ pts) {
    __shared__ int   s_cnt[NCELL];    // 16 KB
    __shared__ int   s_start[NCELL];  // 16 KB
    __shared__ int   s_wsum[32];
    __shared__ float s_red[128];
    __shared__ float s_minx, s_miny, s_invw, s_invh;

    const int tid = threadIdx.x;
    const int lane = tid & 31, warp = tid >> 5;

#pragma unroll
    for (int i = 0; i < NCELL / 1024; i++) s_cnt[tid + i * 1024] = 0;
    if (tid == 0) g_ticket = 0;

    // ---- bbox ----
    float2 loc[NPTS / 1024];
    float mnx = 1e30f, mxx = -1e30f, mny = 1e30f, mxy = -1e30f;
#pragma unroll
    for (int i = 0; i < NPTS / 1024; i++) {
        float2 p = pts[tid + i * 1024];
        loc[i] = p;
        mnx = fminf(mnx, p.x); mxx = fmaxf(mxx, p.x);
        mny = fminf(mny, p.y); mxy = fmaxf(mxy, p.y);
    }
#pragma unroll
    for (int off = 16; off > 0; off >>= 1) {
        mnx = fminf(mnx, __shfl_xor_sync(FULLM, mnx, off));
        mxx = fmaxf(mxx, __shfl_xor_sync(FULLM, mxx, off));
        mny = fminf(mny, __shfl_xor_sync(FULLM, mny, off));
        mxy = fmaxf(mxy, __shfl_xor_sync(FULLM, mxy, off));
    }
    if (lane == 0) {
        s_red[warp] = mnx; s_red[32 + warp] = mxx;
        s_red[64 + warp] = mny; s_red[96 + warp] = mxy;
    }
    __syncthreads();
    if (warp == 0) {   // warp-parallel final reduce
        float a = s_red[lane], bx = s_red[32 + lane];
        float c = s_red[64 + lane], dy = s_red[96 + lane];
#pragma unroll
        for (int off = 16; off > 0; off >>= 1) {
            a  = fminf(a,  __shfl_xor_sync(FULLM, a,  off));
            bx = fmaxf(bx, __shfl_xor_sync(FULLM, bx, off));
            c  = fminf(c,  __shfl_xor_sync(FULLM, c,  off));
            dy = fmaxf(dy, __shfl_xor_sync(FULLM, dy, off));
        }
        if (lane == 0) {
            float w = bx - a, h = dy - c;
            s_minx = a; g_minx = a;
            s_miny = c; g_miny = c;
            float iw = (w > 0.0f) ? (float)G / w : 0.0f;
            float ih = (h > 0.0f) ? (float)G / h : 0.0f;
            s_invw = iw; g_invw = iw;
            s_invh = ih; g_invh = ih;
            g_cwmin = fminf(w / (float)G, h / (float)G);
        }
    }
    __syncthreads();

    // ---- count ----
    int mycell[NPTS / 1024];
#pragma unroll
    for (int i = 0; i < NPTS / 1024; i++) {
        int cx = min(max((int)((loc[i].x - s_minx) * s_invw), 0), G - 1);
        int cy = min(max((int)((loc[i].y - s_miny) * s_invh), 0), G - 1);
        int c = cy * G + cx;
        mycell[i] = c;
        atomicAdd(&s_cnt[c], 1);
    }
    __syncthreads();

    // ---- prefix scan: 4 cells/thread + shfl warp scan + cross-warp scan ----
    int v[4], run = 0;
    const int base = tid * 4;
#pragma unroll
    for (int i = 0; i < 4; i++) { v[i] = run; run += s_cnt[base + i]; }
    int inc = run;
#pragma unroll
    for (int off = 1; off < 32; off <<= 1) {
        int y = __shfl_up_sync(FULLM, inc, off);
        if (lane >= off) inc += y;
    }
    if (lane == 31) s_wsum[warp] = inc;
    __syncthreads();
    if (warp == 0) {
        int x = s_wsum[lane];
#pragma unroll
        for (int off = 1; off < 32; off <<= 1) {
            int y = __shfl_up_sync(FULLM, x, off);
            if (lane >= off) x += y;
        }
        s_wsum[lane] = x;
    }
    __syncthreads();
    int pre = ((warp > 0) ? s_wsum[warp - 1] : 0) + inc - run;
#pragma unroll
    for (int i = 0; i < 4; i++) {
        int st = pre + v[i];
        s_start[base + i] = st;
        g_cellinfo[base + i] = make_int2(st, s_cnt[base + i]);
    }
    __syncthreads();

    // ---- scatter (atomic cursor; downstream is order-independent) ----
#pragma unroll
    for (int i = 0; i < NPTS / 1024; i++) {
        int slot = atomicAdd(&s_start[mycell[i]], 1);
        g_pts4[slot] = make_float4(loc[i].x, loc[i].y,
                                   __int_as_float(tid + i * 1024), 0.0f);
    }
}

// ======================= K2: search (warp per query) ===================
#define STPB 256
#define SWPB (STPB / 32)            // 8 warps/CTA
#define SNBLK (NPTS / SWPB)         // 1024 CTAs

// Coalesced scan of contiguous slot range [rs, re): lanes stride points.
__device__ __forceinline__ void scan_range(int rs, int re, float qx, float qy,
                                           float th, ull* b, int lane) {
    for (int j = rs + lane; j < re; j += 32) {
        float4 P = g_pts4[j];
        float dx = qx - P.x;
        float dy = qy - P.y;
        float d2 = fmaf(dx, dx, dy * dy);
        if (d2 <= th) {  // <= so boundary ties resolve exactly via key
            ull key = ((ull)__float_as_uint(d2) << 32) |
                      (unsigned)__float_as_int(P.z);
            if (key < b[5]) {
                b[5] = key;
#pragma unroll
                for (int t = 5; t > 0; t--) {
                    if (b[t] < b[t - 1]) {
                        ull tmp = b[t]; b[t] = b[t - 1]; b[t - 1] = tmp;
                    }
                }
            }
        }
    }
}

// Exact warp merge: fold previous ranks rk into lane-local lists, then 6
// warp-min extraction rounds. Unique keys -> exact, order-independent.
__device__ __forceinline__ void merge6(ull* b, ull& rk, float& th, int lane) {
    if (lane < 6 && rk != SENT && rk < b[5]) {
        b[5] = rk;
#pragma unroll
        for (int t = 5; t > 0; t--) {
            if (b[t] < b[t - 1]) { ull tmp = b[t]; b[t] = b[t - 1]; b[t - 1] = tmp; }
        }
    }
    ull newrk = SENT;
#pragma unroll
    for (int r = 0; r < 6; r++) {
        ull m = b[0];
#pragma unroll
        for (int off = 16; off > 0; off >>= 1) {
            ull o = __shfl_xor_sync(FULLM, m, off);
            if (o < m) m = o;
        }
        if (lane == r) newrk = m;
        if (b[0] == m && m != SENT) {
            b[0] = b[1]; b[1] = b[2]; b[2] = b[3];
            b[3] = b[4]; b[4] = b[5]; b[5] = SENT;
        }
    }
    rk = newrk;
    ull k5 = __shfl_sync(FULLM, rk, 5);
    th = (k5 == SENT) ? __int_as_float(0x7F800000)
                      : __uint_as_float((unsigned)(k5 >> 32));
}

__global__ __launch_bounds__(STPB)
void search_kernel(const float* __restrict__ outputs,
                   const float2* __restrict__ pts,
                   float* __restrict__ out) {
    const int i = blockIdx.x * SWPB + (threadIdx.x >> 5);  // query index
    const int lane = threadIdx.x & 31;

    const float2 q = pts[i];
    const float cw = g_cwmin;
    const int cx = min(max((int)((q.x - g_minx) * g_invw), 0), G - 1);
    const int cy = min(max((int)((q.y - g_miny) * g_invh), 0), G - 1);

    ull b[6];
#pragma unroll
    for (int t = 0; t < 6; t++) b[t] = SENT;
    ull rk = SENT;
    float th = __int_as_float(0x7F800000);

    // ---- disk D=1: up to 3 contiguous row ranges ----
    {
        int xa = max(cx - 1, 0), xb = min(cx + 1, G - 1);
        int ya = max(cy - 1, 0), yb = min(cy + 1, G - 1);
        for (int y = ya; y <= yb; y++) {
            int2 c0 = g_cellinfo[y * G + xa];
            int2 c1 = g_cellinfo[y * G + xb];
            scan_range(c0.x, c1.x + c1.y, q.x, q.y, th, b, lane);
        }
    }
    merge6(b, rk, th, lane);

    // ---- expanding rings with exact termination bound ----
    int D = 1;
    while (D < G) {
        float bnd = (float)D * cw;
        if (th <= bnd * bnd) break;  // unscanned rings >= D+1 -> dist >= D*cw
        const int d = D + 1;
        int xa = max(cx - d, 0), xb = min(cx + d, G - 1);
        if (cy - d >= 0) {
            int y = cy - d;
            int2 c0 = g_cellinfo[y * G + xa];
            int2 c1 = g_cellinfo[y * G + xb];
            scan_range(c0.x, c1.x + c1.y, q.x, q.y, th, b, lane);
        }
        if (cy + d <= G - 1) {
            int y = cy + d;
            int2 c0 = g_cellinfo[y * G + xa];
            int2 c1 = g_cellinfo[y * G + xb];
            scan_range(c0.x, c1.x + c1.y, q.x, q.y, th, b, lane);
        }
        int ya = max(cy - d + 1, 0), yb = min(cy + d - 1, G - 1);
        for (int y = ya; y <= yb; y++) {
            if (cx - d >= 0) {
                int2 c = g_cellinfo[y * G + cx - d];
                scan_range(c.x, c.x + c.y, q.x, q.y, th, b, lane);
            }
            if (cx + d <= G - 1) {
                int2 c = g_cellinfo[y * G + cx + d];
                scan_range(c.x, c.x + c.y, q.x, q.y, th, b, lane);
            }
        }
        merge6(b, rk, th, lane);
        D = d;
    }

    // ---- epilogue: rank 0 = self (min key); lanes 1..5 own neighbors ----
    {
        float s = 0.0f;
        if (lane >= 1 && lane <= KNN) {
            int nb = (int)(rk & 0xFFFFFFFFULL);
            const float4* oq = (const float4*)(outputs + (size_t)i * NCH);
            const float4* on = (const float4*)(outputs + (size_t)nb * NCH);
            float acc = 0.0f;
#pragma unroll
            for (int c = 0; c < NCH / 4; c++) {
                float4 a = oq[c];
                float4 bb = on[c];
                float d;
                d = a.x - bb.x; acc = fmaf(d, d, acc);
                d = a.y - bb.y; acc = fmaf(d, d, acc);
                d = a.z - bb.z; acc = fmaf(d, d, acc);
                d = a.w - bb.w; acc = fmaf(d, d, acc);
            }
            s = sqrtf(acc);
        }
#pragma unroll
        for (int off = 16; off > 0; off >>= 1)
            s += __shfl_xor_sync(FULLM, s, off);
        if (lane == 0) g_partial[i] = s;
    }

    // ---- fused final reduction: last CTA does a fixed-order sum ----
    __syncthreads();
    __shared__ bool is_last;
    if (threadIdx.x == 0) {
        __threadfence();
        unsigned tk = atomicAdd(&g_ticket, 1);
        is_last = (tk == SNBLK - 1);
    }
    __syncthreads();
    if (is_last) {
        __threadfence();
        float acc = 0.0f;
        for (int j = threadIdx.x; j < NPTS; j += STPB) acc += g_partial[j];
        __shared__ float sm[STPB];
        sm[threadIdx.x] = acc;
        __syncthreads();
        for (int st = STPB / 2; st > 0; st >>= 1) {
            if (threadIdx.x < st) sm[threadIdx.x] += sm[threadIdx.x + st];
            __syncthreads();
        }
        if (threadIdx.x == 0) {
            out[0] = sm[0] / (float)(NPTS * KNN);
            g_ticket = 0;  // reset for next graph replay
        }
    }
}

extern "C" void kernel_launch(void* const* d_in, const int* in_sizes, int n_in,
                              void* d_out, int out_size) {
    const float*  outputs = (const float*)d_in[0];
    const float2* points  = (const float2*)d_in[1];
    float* out = (float*)d_out;

    build_kernel<<<1, 1024>>>(points);
    search_kernel<<<SNBLK, STPB>>>(outputs, points, out);
}

// round 10
// speedup vs baseline: 1.1173x; 1.1173x over previous
#include <cuda_runtime.h>
#include <cstdint>

// GeometricLoss via spatial grid, R10:
//  K1 build (1 CTA): bbox -> smem bin count -> shfl prefix scan -> scatter
//     into g_pts4 {x,y,pid,0} + g_cellinfo {start,count}.
//  K2 search: one warp per BINNED slot (spatial locality). Disk D=1 scanned
//     as a flattened union of <=3 contiguous row ranges (one parallel load
//     round). Exact top-6 extraction via __reduce_min_sync on (d2_bits, pid).
//     Expanding rings (rare) with exact termination bound.
// Keys (d2_bits, pid) unique & totally ordered -> order-independent exact
// selection, jax.lax.top_k low-index tie-break, deterministic output
// (g_partial indexed by pid, fixed-order reduction).

#define NPTS 8192
#define NCH 16
#define KNN 5
#define G 64
#define NCELL (G * G)
#define FULLM 0xFFFFFFFFu
typedef unsigned long long ull;
#define SENT 0xFFFFFFFFFFFFFFFFULL

__device__ float4 g_pts4[NPTS];       // {x, y, bitcast(pid), 0}
__device__ int2   g_cellinfo[NCELL];  // {start, count}
__device__ float  g_partial[NPTS];    // indexed by ORIGINAL pid
__device__ unsigned g_ticket;
__device__ float g_minx, g_miny, g_invw, g_invh, g_cwmin;

// ======================= K1: build (single CTA) =======================
__global__ __launch_bounds__(1024, 1)
void build_kernel(const float2* __restrict__ pts) {
    __shared__ int   s_cnt[NCELL];    // 16 KB
    __shared__ int   s_start[NCELL];  // 16 KB
    __shared__ int   s_wsum[32];
    __shared__ float s_red[128];
    __shared__ float s_minx, s_miny, s_invw, s_invh;

    const int tid = threadIdx.x;
    const int lane = tid & 31, warp = tid >> 5;

#pragma unroll
    for (int i = 0; i < NCELL / 1024; i++) s_cnt[tid + i * 1024] = 0;
    if (tid == 0) g_ticket = 0;

    // ---- bbox ----
    float2 loc[NPTS / 1024];
    float mnx = 1e30f, mxx = -1e30f, mny = 1e30f, mxy = -1e30f;
#pragma unroll
    for (int i = 0; i < NPTS / 1024; i++) {
        float2 p = pts[tid + i * 1024];
        loc[i] = p;
        mnx = fminf(mnx, p.x); mxx = fmaxf(mxx, p.x);
        mny = fminf(mny, p.y); mxy = fmaxf(mxy, p.y);
    }
#pragma unroll
    for (int off = 16; off > 0; off >>= 1) {
        mnx = fminf(mnx, __shfl_xor_sync(FULLM, mnx, off));
        mxx = fmaxf(mxx, __shfl_xor_sync(FULLM, mxx, off));
        mny = fminf(mny, __shfl_xor_sync(FULLM, mny, off));
        mxy = fmaxf(mxy, __shfl_xor_sync(FULLM, mxy, off));
    }
    if (lane == 0) {
        s_red[warp] = mnx; s_red[32 + warp] = mxx;
        s_red[64 + warp] = mny; s_red[96 + warp] = mxy;
    }
    __syncthreads();
    if (warp == 0) {
        float a = s_red[lane], bx = s_red[32 + lane];
        float c = s_red[64 + lane], dy = s_red[96 + lane];
#pragma unroll
        for (int off = 16; off > 0; off >>= 1) {
            a  = fminf(a,  __shfl_xor_sync(FULLM, a,  off));
            bx = fmaxf(bx, __shfl_xor_sync(FULLM, bx, off));
            c  = fminf(c,  __shfl_xor_sync(FULLM, c,  off));
            dy = fmaxf(dy, __shfl_xor_sync(FULLM, dy, off));
        }
        if (lane == 0) {
            float w = bx - a, h = dy - c;
            s_minx = a; g_minx = a;
            s_miny = c; g_miny = c;
            float iw = (w > 0.0f) ? (float)G / w : 0.0f;
            float ih = (h > 0.0f) ? (float)G / h : 0.0f;
            s_invw = iw; g_invw = iw;
            s_invh = ih; g_invh = ih;
            g_cwmin = fminf(w / (float)G, h / (float)G);
        }
    }
    __syncthreads();

    // ---- count ----
    int mycell[NPTS / 1024];
#pragma unroll
    for (int i = 0; i < NPTS / 1024; i++) {
        int cx = min(max((int)((loc[i].x - s_minx) * s_invw), 0), G - 1);
        int cy = min(max((int)((loc[i].y - s_miny) * s_invh), 0), G - 1);
        int c = cy * G + cx;
        mycell[i] = c;
        atomicAdd(&s_cnt[c], 1);
    }
    __syncthreads();

    // ---- prefix scan: 4 cells/thread + shfl warp scan + cross-warp scan ----
    int v[4], run = 0;
    const int base = tid * 4;
#pragma unroll
    for (int i = 0; i < 4; i++) { v[i] = run; run += s_cnt[base + i]; }
    int inc = run;
#pragma unroll
    for (int off = 1; off < 32; off <<= 1) {
        int y = __shfl_up_sync(FULLM, inc, off);
        if (lane >= off) inc += y;
    }
    if (lane == 31) s_wsum[warp] = inc;
    __syncthreads();
    if (warp == 0) {
        int x = s_wsum[lane];
#pragma unroll
        for (int off = 1; off < 32; off <<= 1) {
            int y = __shfl_up_sync(FULLM, x, off);
            if (lane >= off) x += y;
        }
        s_wsum[lane] = x;
    }
    __syncthreads();
    int pre = ((warp > 0) ? s_wsum[warp - 1] : 0) + inc - run;
#pragma unroll
    for (int i = 0; i < 4; i++) {
        int st = pre + v[i];
        s_start[base + i] = st;
        g_cellinfo[base + i] = make_int2(st, s_cnt[base + i]);
    }
    __syncthreads();

    // ---- scatter (atomic cursor; downstream is order-independent) ----
#pragma unroll
    for (int i = 0; i < NPTS / 1024; i++) {
        int slot = atomicAdd(&s_start[mycell[i]], 1);
        g_pts4[slot] = make_float4(loc[i].x, loc[i].y,
                                   __int_as_float(tid + i * 1024), 0.0f);
    }
}

// ======================= K2: search (warp per binned slot) =============
#define STPB 256
#define SWPB (STPB / 32)            // 8 warps/CTA
#define SNBLK (NPTS / SWPB)         // 1024 CTAs

// Per-lane sorted top-6 insert (raw d2 bits in high word: d2 >= 0).
__device__ __forceinline__ void ins6(ull* b, float d2, unsigned pid) {
    ull key = ((ull)__float_as_uint(d2) << 32) | pid;
    if (key < b[5]) {
        b[5] = key;
#pragma unroll
        for (int t = 5; t > 0; t--) {
            if (b[t] < b[t - 1]) { ull tmp = b[t]; b[t] = b[t - 1]; b[t - 1] = tmp; }
        }
    }
}

// Exact global top-6 extraction across the warp using REDUX.MIN.U32:
// round r: min d2-bits, then min pid among d2 ties. Unique (d2,pid) keys ->
// exact selection, low-index tie-break. Updates rk (lane r holds rank r)
// and th (6th-best d2, +inf if fewer than 6 found so far).
__device__ __forceinline__ void extract6(ull* b, ull& rk, float& th, int lane) {
    // fold previous global ranks back into lane-local lists
    if (lane < 6 && rk != SENT && rk < b[5]) {
        b[5] = rk;
#pragma unroll
        for (int t = 5; t > 0; t--) {
            if (b[t] < b[t - 1]) { ull tmp = b[t]; b[t] = b[t - 1]; b[t - 1] = tmp; }
        }
    }
    ull newrk = SENT;
#pragma unroll
    for (int r = 0; r < 6; r++) {
        unsigned hi = (unsigned)(b[0] >> 32);
        unsigned mhi = __reduce_min_sync(FULLM, hi);
        unsigned lo = (hi == mhi) ? (unsigned)(b[0] & 0xFFFFFFFFULL)
                                  : 0xFFFFFFFFu;
        unsigned mlo = __reduce_min_sync(FULLM, lo);
        ull win = ((ull)mhi << 32) | mlo;
        if (lane == r) newrk = win;
        if (b[0] == win) {  // unique key: at most the one owner advances
            b[0] = b[1]; b[1] = b[2]; b[2] = b[3];
            b[3] = b[4]; b[4] = b[5]; b[5] = SENT;
        }
    }
    rk = newrk;
    ull k5 = __shfl_sync(FULLM, newrk, 5);
    unsigned hi5 = (unsigned)(k5 >> 32);
    th = (hi5 == 0xFFFFFFFFu) ? __int_as_float(0x7F800000)
                              : __uint_as_float(hi5);
}

__global__ __launch_bounds__(STPB)
void search_kernel(const float* __restrict__ outputs,
                   float* __restrict__ out) {
    const int slot = blockIdx.x * SWPB + (threadIdx.x >> 5);
    const int lane = threadIdx.x & 31;

    const float4 Q = g_pts4[slot];      // broadcast load
    const float qx = Q.x, qy = Q.y;
    const unsigned qpid = (unsigned)__float_as_int(Q.z);
    const float cw = g_cwmin;
    const int cx = min(max((int)((qx - g_minx) * g_invw), 0), G - 1);
    const int cy = min(max((int)((qy - g_miny) * g_invh), 0), G - 1);

    ull b[6];
#pragma unroll
    for (int t = 0; t < 6; t++) b[t] = SENT;
    ull rk = SENT;
    float th = __int_as_float(0x7F800000);

    // ---- disk D=1: flattened union of <=3 contiguous row ranges ----
    {
        int xa = max(cx - 1, 0), xb = min(cx + 1, G - 1);
        int ya = max(cy - 1, 0), yb = min(cy + 1, G - 1);
        int s0 = 0, l0 = 0, s1 = 0, l1 = 0, s2 = 0, l2 = 0;
        {
            int2 c0 = g_cellinfo[ya * G + xa];
            int2 c1 = g_cellinfo[ya * G + xb];
            s0 = c0.x; l0 = c1.x + c1.y - c0.x;
        }
        if (ya + 1 <= yb) {
            int2 c0 = g_cellinfo[(ya + 1) * G + xa];
            int2 c1 = g_cellinfo[(ya + 1) * G + xb];
            s1 = c0.x; l1 = c1.x + c1.y - c0.x;
        }
        if (ya + 2 <= yb) {
            int2 c0 = g_cellinfo[(ya + 2) * G + xa];
            int2 c1 = g_cellinfo[(ya + 2) * G + xb];
            s2 = c0.x; l2 = c1.x + c1.y - c0.x;
        }
        int o1 = l0, o2 = l0 + l1, tot = o2 + l2;
        for (int t = lane; t < tot; t += 32) {
            int j;
            if (t < o1)      j = s0 + t;
            else if (t < o2) j = s1 + (t - o1);
            else             j = s2 + (t - o2);
            float4 P = g_pts4[j];
            float dx = qx - P.x;
            float dy = qy - P.y;
            float d2 = fmaf(dx, dx, dy * dy);
            ins6(b, d2, (unsigned)__float_as_int(P.z));
        }
    }
    extract6(b, rk, th, lane);

    // ---- expanding rings (rare) with exact termination bound ----
    int D = 1;
    while (D < G) {
        float bnd = (float)D * cw;
        if (th <= bnd * bnd) break;  // unscanned rings >= D+1 -> dist >= D*cw
        const int d = D + 1;
        int xa = max(cx - d, 0), xb = min(cx + d, G - 1);
        if (cy - d >= 0) {
            int y = cy - d;
            int2 c0 = g_cellinfo[y * G + xa];
            int2 c1 = g_cellinfo[y * G + xb];
            for (int j = c0.x + lane; j < c1.x + c1.y; j += 32) {
                float4 P = g_pts4[j];
                float dx = qx - P.x, dy = qy - P.y;
                float d2 = fmaf(dx, dx, dy * dy);
                if (d2 <= th) ins6(b, d2, (unsigned)__float_as_int(P.z));
            }
        }
        if (cy + d <= G - 1) {
            int y = cy + d;
            int2 c0 = g_cellinfo[y * G + xa];
            int2 c1 = g_cellinfo[y * G + xb];
            for (int j = c0.x + lane; j < c1.x + c1.y; j += 32) {
                float4 P = g_pts4[j];
                float dx = qx - P.x, dy = qy - P.y;
                float d2 = fmaf(dx, dx, dy * dy);
                if (d2 <= th) ins6(b, d2, (unsigned)__float_as_int(P.z));
            }
        }
        int ya = max(cy - d + 1, 0), yb = min(cy + d - 1, G - 1);
        for (int y = ya; y <= yb; y++) {
            if (cx - d >= 0) {
                int2 c = g_cellinfo[y * G + cx - d];
                for (int j = c.x + lane; j < c.x + c.y; j += 32) {
                    float4 P = g_pts4[j];
                    float dx = qx - P.x, dy = qy - P.y;
                    float d2 = fmaf(dx, dx, dy * dy);
                    if (d2 <= th) ins6(b, d2, (unsigned)__float_as_int(P.z));
                }
            }
            if (cx + d <= G - 1) {
                int2 c = g_cellinfo[y * G + cx + d];
                for (int j = c.x + lane; j < c.x + c.y; j += 32) {
                    float4 P = g_pts4[j];
                    float dx = qx - P.x, dy = qy - P.y;
                    float d2 = fmaf(dx, dx, dy * dy);
                    if (d2 <= th) ins6(b, d2, (unsigned)__float_as_int(P.z));
                }
            }
        }
        extract6(b, rk, th, lane);
        D = d;
    }

    // ---- epilogue: rank 0 = self (d2=0 min key); lanes 1..5 = neighbors ----
    {
        float s = 0.0f;
        if (lane >= 1 && lane <= KNN) {
            int nb = (int)(rk & 0xFFFFFFFFULL);
            const float4* oq = (const float4*)(outputs + (size_t)qpid * NCH);
            const float4* on = (const float4*)(outputs + (size_t)nb * NCH);
            float acc = 0.0f;
#pragma unroll
            for (int c = 0; c < NCH / 4; c++) {
                float4 a = oq[c];
                float4 bb = on[c];
                float d;
                d = a.x - bb.x; acc = fmaf(d, d, acc);
                d = a.y - bb.y; acc = fmaf(d, d, acc);
                d = a.z - bb.z; acc = fmaf(d, d, acc);
                d = a.w - bb.w; acc = fmaf(d, d, acc);
            }
            s = sqrtf(acc);
        }
#pragma unroll
        for (int off = 16; off > 0; off >>= 1)
            s += __shfl_xor_sync(FULLM, s, off);
        if (lane == 0) g_partial[qpid] = s;   // pid-indexed: fixed sum order
    }

    // ---- fused final reduction: last CTA does a fixed-order sum ----
    __syncthreads();
    __shared__ bool is_last;
    if (threadIdx.x == 0) {
        __threadfence();
        unsigned tk = atomicAdd(&g_ticket, 1);
        is_last = (tk == SNBLK - 1);
    }
    __syncthreads();
    if (is_last) {
        __threadfence();
        float acc = 0.0f;
        for (int j = threadIdx.x; j < NPTS; j += STPB) acc += g_partial[j];
        __shared__ float sm[STPB];
        sm[threadIdx.x] = acc;
        __syncthreads();
        for (int st = STPB / 2; st > 0; st >>= 1) {
            if (threadIdx.x < st) sm[threadIdx.x] += sm[threadIdx.x + st];
            __syncthreads();
        }
        if (threadIdx.x == 0) {
            out[0] = sm[0] / (float)(NPTS * KNN);
            g_ticket = 0;  // reset for next graph replay
        }
    }
}

extern "C" void kernel_launch(void* const* d_in, const int* in_sizes, int n_in,
                              void* d_out, int out_size) {
    const float*  outputs = (const float*)d_in[0];
    const float2* points  = (const float2*)d_in[1];
    float* out = (float*)d_out;

    build_kernel<<<1, 1024>>>(points);
    search_kernel<<<SNBLK, STPB>>>(outputs, out);
}